// round 11
// baseline (speedup 1.0000x reference)
#include <cuda_runtime.h>
#include <cuda_fp16.h>
#include <cstdint>
#include <cstddef>

// Problem constants
#define BB 8
#define NSEQ 4096
#define NN 32768            // BB*NSEQ nodes
#define H 128
#define EDGES 524288
#define RREL 8
#define NLAYERS 2

#define PITCH_W 136         // fp16 elems per smem row (272B)

// ---- smem map (fp16 element offsets): A (64 rows) + Wh (128 rows) + Wl (128 rows) ----
#define A_OFF 0
#define W_H   (64 * PITCH_W)                   // 8704
#define W_L   (W_H + 128 * PITCH_W)            // 26112
#define SM1_BYTES ((W_H + 128 * PITCH_W) * 2)  // 1-chain: 52224 B
#define SM2_BYTES ((W_L + 128 * PITCH_W) * 2)  // 2-chain: 87040 B

#define NMAT (1 + NLAYERS * (RREL + 1))        // 19 weight matrices
#define SCALE 64.0f
#define INV_SCALE2 (1.0f / 4096.0f)

// ---------------- scratch (static device globals; no allocation) ----------------
__device__ float g_Z[(size_t)NN * H];            // self-GEMM out / agg accumulator (16 MB)
__device__ __half g_Y[(size_t)RREL * NN * H];    // per-relation messages, fp16 (64 MB)
__device__ __half g_Xf[(size_t)NN * H];          // node states, fp16 scaled x64 (8 MB)
__device__ __half g_Wh[(size_t)NMAT * H * H];    // weight hi splits (x64)
__device__ __half g_Wl[(size_t)NMAT * H * H];    // weight lo splits
__device__ float g_deg[NN];

// ---------------- helpers ----------------
__device__ __forceinline__ uint32_t smem_u32(const void* p) {
    uint32_t a;
    asm("{ .reg .u64 t; cvta.to.shared.u64 t, %1; cvt.u32.u64 %0, t; }" : "=r"(a) : "l"(p));
    return a;
}
__device__ __forceinline__ void cp_async16(uint32_t dst, const void* src) {
    asm volatile("cp.async.cg.shared.global [%0], [%1], 16;" :: "r"(dst), "l"(src));
}
__device__ __forceinline__ void cp_commit() {
    asm volatile("cp.async.commit_group;");
}
__device__ __forceinline__ void cp_wait0() {
    asm volatile("cp.async.wait_group 0;");
}
__device__ __forceinline__ void ldm_x4(uint32_t& r0, uint32_t& r1, uint32_t& r2, uint32_t& r3,
                                       uint32_t addr) {
    asm volatile("ldmatrix.sync.aligned.m8n8.x4.shared.b16 {%0,%1,%2,%3}, [%4];"
                 : "=r"(r0), "=r"(r1), "=r"(r2), "=r"(r3) : "r"(addr));
}
__device__ __forceinline__ void mma16816(float* d, const uint32_t* a, uint32_t b0, uint32_t b1) {
    asm volatile(
        "mma.sync.aligned.m16n8k16.row.col.f32.f16.f16.f32 "
        "{%0,%1,%2,%3}, {%4,%5,%6,%7}, {%8,%9}, {%0,%1,%2,%3};"
        : "+f"(d[0]), "+f"(d[1]), "+f"(d[2]), "+f"(d[3])
        : "r"(a[0]), "r"(a[1]), "r"(a[2]), "r"(a[3]), "r"(b0), "r"(b1));
}
__device__ __forceinline__ void split_h16(float v, __half& hi, __half& lo) {
    hi = __float2half(v);
    lo = __float2half(v - __half2float(hi));
}

// ---------------- embed: Xf = fp16(64*(concept_emb[cid]+kind_emb[kid])); zero deg ------
__global__ __launch_bounds__(256) void embed_kernel(const int* __restrict__ cid,
                                                    const int* __restrict__ kid,
                                                    const float* __restrict__ cemb,
                                                    const float* __restrict__ kemb) {
    int t = blockIdx.x * 256 + threadIdx.x;        // one float4 per thread
    if (t < NN) g_deg[t] = 0.0f;
    int node = t >> 5;
    int q = t & 31;
    int c = __ldg(cid + node);
    int k = __ldg(kid + node);
    float4 a = __ldg(((const float4*)(cemb + (size_t)c * H)) + q);
    float4 b = __ldg(((const float4*)(kemb + (size_t)k * H)) + q);
    __half h[4];
    h[0] = __float2half(SCALE * (a.x + b.x));
    h[1] = __float2half(SCALE * (a.y + b.y));
    h[2] = __float2half(SCALE * (a.z + b.z));
    h[3] = __float2half(SCALE * (a.w + b.w));
    ((uint2*)g_Xf)[t] = *(const uint2*)h;
}

// ---------------- degree ----------------
__global__ __launch_bounds__(256) void deg_kernel(const int* __restrict__ eidx) {
    int e = blockIdx.x * 256 + threadIdx.x;
    if (e < EDGES) atomicAdd(&g_deg[__ldg(eidx + EDGES + e)], 1.0f);
}

// ---------------- all-weight split conversion (proj + both layers, one launch) --------
// layout: [proj][L0: rel0..7, self][L1: rel0..7, self], each 16384 elems
__global__ __launch_bounds__(256) void convert_w_all_kernel(const float* __restrict__ projW,
                                                            const float* __restrict__ selfW,
                                                            const float* __restrict__ relW) {
    int t = blockIdx.x * 256 + threadIdx.x;
    int f8 = t * 8;
    if (f8 >= NMAT * H * H) return;
    const float* src;
    if (f8 < H * H) {
        src = projW + f8;
    } else {
        int g = f8 - H * H;
        int l = g / ((RREL + 1) * H * H);
        int r = g % ((RREL + 1) * H * H);
        if (r < RREL * H * H) src = relW + (size_t)l * RREL * H * H + r;
        else src = selfW + (size_t)l * H * H + (r - RREL * H * H);
    }
    float4 a = *(const float4*)src;
    float4 b = *(const float4*)(src + 4);
    float v[8] = {a.x, a.y, a.z, a.w, b.x, b.y, b.z, b.w};
    __half hi[8], lo[8];
#pragma unroll
    for (int i = 0; i < 8; i++) split_h16(SCALE * v[i], hi[i], lo[i]);
    ((uint4*)g_Wh)[t] = *(const uint4*)hi;
    ((uint4*)g_Wl)[t] = *(const uint4*)lo;
}

// ---------------- 64x128x128 fp16 HMMA tile GEMM (fully smem-resident) ----------------
// O[m][g] = sum_k A[m][k]*W[g][k] (scaled ops; /4096 + bias in epilogue).
// Tile: 64 rows x 128 cols, K=128 all resident. 8 warps: wm=wid>>2 (32-row blk),
// wn=wid&3 (32-col blk). acc[2][4][4] = 32 regs/thread.
// CHAINS=2: a*wh + a*wl. CHAINS=1: a*wh only.
// OUT_MODE 0: fp32 -> O (+bias).  OUT_MODE 1: fp16 x64 -> Oh (+bias; in-place over A ok).
// OUT_MODE 2: fp16 unscaled -> Oh (no bias).
template <int OUT_MODE, int CHAINS>
__device__ __forceinline__ void tile_gemm64(const __half* __restrict__ A_g,
                                            const __half* __restrict__ Wh_g,
                                            const __half* __restrict__ Wl_g,
                                            const float* __restrict__ bias,
                                            float* __restrict__ O,
                                            __half* __restrict__ Oh, int m0) {
    extern __shared__ __half sm[];
    const uint32_t sbase = smem_u32(sm);
    const int tid = threadIdx.x;
    const __half* Ag = A_g + (size_t)m0 * H;

    // ---- prologue: A tile (64x128 = 1024 chunks) + W hi (2048) + W lo (2048 if 2-chain)
#pragma unroll
    for (int it = 0; it < 4; it++) {
        int i = tid + it * 256;           // 0..1023, 16 chunks per row
        int r = i >> 4;
        int c = i & 15;
        cp_async16(sbase + (A_OFF + r * PITCH_W + c * 8) * 2, Ag + r * H + c * 8);
    }
#pragma unroll
    for (int it = 0; it < 8; it++) {
        int i = tid + it * 256;           // 0..2047
        int r = i >> 4;
        int c = i & 15;
        cp_async16(sbase + (W_H + r * PITCH_W + c * 8) * 2, Wh_g + r * H + c * 8);
    }
    if (CHAINS == 2) {
#pragma unroll
        for (int it = 0; it < 8; it++) {
            int i = tid + it * 256;
            int r = i >> 4;
            int c = i & 15;
            cp_async16(sbase + (W_L + r * PITCH_W + c * 8) * 2, Wl_g + r * H + c * 8);
        }
    }
    cp_commit();
    cp_wait0();
    __syncthreads();

    const int wid = tid >> 5;
    const int lane = tid & 31;
    const int wm = wid >> 2;       // 0..1 : 32-row block
    const int wn = wid & 3;        // 0..3 : 32-col block

    float acc[2][4][4];
#pragma unroll
    for (int i = 0; i < 2; i++)
#pragma unroll
        for (int j = 0; j < 4; j++)
#pragma unroll
            for (int k = 0; k < 4; k++) acc[i][j][k] = 0.0f;

    const uint32_t lrow = lane & 15;
    const uint32_t lhalf = lane >> 4;          // 0/1 -> +8 fp16
    const uint32_t aA  = sbase + (A_OFF + (wm * 32 + lrow) * PITCH_W + lhalf * 8) * 2;
    const uint32_t aWh = sbase + (W_H + (wn * 32 + lrow) * PITCH_W + lhalf * 8) * 2;
    const uint32_t aWl = sbase + (W_L + (wn * 32 + lrow) * PITCH_W + lhalf * 8) * 2;

#pragma unroll
    for (int ks = 0; ks < 8; ks++) {
        const uint32_t koff = ks * 32;         // 16 fp16 = 32 bytes
        uint32_t bh[2][4], bl[2][4];
#pragma unroll
        for (int bi = 0; bi < 2; bi++) {
            ldm_x4(bh[bi][0], bh[bi][1], bh[bi][2], bh[bi][3],
                   aWh + bi * (16 * PITCH_W * 2) + koff);
            if (CHAINS == 2) {
                ldm_x4(bl[bi][0], bl[bi][1], bl[bi][2], bl[bi][3],
                       aWl + bi * (16 * PITCH_W * 2) + koff);
            }
        }
#pragma unroll
        for (int mi = 0; mi < 2; mi++) {
            uint32_t a[4];
            ldm_x4(a[0], a[1], a[2], a[3], aA + mi * (16 * PITCH_W * 2) + koff);
#pragma unroll
            for (int bi = 0; bi < 2; bi++) {
                mma16816(acc[mi][2 * bi + 0], a, bh[bi][0], bh[bi][2]);
                mma16816(acc[mi][2 * bi + 1], a, bh[bi][1], bh[bi][3]);
                if (CHAINS == 2) {
                    mma16816(acc[mi][2 * bi + 0], a, bl[bi][0], bl[bi][2]);
                    mma16816(acc[mi][2 * bi + 1], a, bl[bi][1], bl[bi][3]);
                }
            }
        }
    }

    // epilogue: unscale (/4096), add bias (modes 0/1)
    const int gID = lane >> 2;
    const int tig = lane & 3;
#pragma unroll
    for (int mi = 0; mi < 2; mi++) {
#pragma unroll
        for (int nt = 0; nt < 4; nt++) {
            int col = wn * 32 + nt * 8 + tig * 2;
            float b0 = 0.0f, b1 = 0.0f;
            if (OUT_MODE != 2 && bias) { b0 = __ldg(bias + col); b1 = __ldg(bias + col + 1); }
#pragma unroll
            for (int half = 0; half < 2; half++) {
                int row = m0 + wm * 32 + mi * 16 + gID + half * 8;
                float v0 = acc[mi][nt][2 * half + 0] * INV_SCALE2 + b0;
                float v1 = acc[mi][nt][2 * half + 1] * INV_SCALE2 + b1;
                if (OUT_MODE == 0) {
                    float2 fv = make_float2(v0, v1);
                    *(float2*)(O + (size_t)row * H + col) = fv;
                } else if (OUT_MODE == 1) {
                    __half2 hv;
                    hv.x = __float2half(SCALE * v0);
                    hv.y = __float2half(SCALE * v1);
                    *(__half2*)(Oh + (size_t)row * H + col) = hv;
                } else {
                    __half2 hv;
                    hv.x = __float2half(v0);
                    hv.y = __float2half(v1);
                    *(__half2*)(Oh + (size_t)row * H + col) = hv;
                }
            }
        }
    }
}

// proj: Xf = fp16 x64 of (E0 @ projW^T + projb), in-place over Xf (2-chain)
__global__ __launch_bounds__(256, 2) void mma_proj_kernel(const float* __restrict__ projb) {
    tile_gemm64<1, 2>(g_Xf, g_Wh, g_Wl, projb, nullptr, g_Xf, blockIdx.x * 64);
}

// relation GEMMs: grid (512, 8); Y[r] = X @ rel_W[r]^T, 1-chain, fp16 out; 4 CTAs/SM
__global__ __launch_bounds__(256, 4) void mma_rel_kernel(int l) {
    int m = blockIdx.y;
    size_t woff = (size_t)(1 + l * (RREL + 1) + m) * H * H;
    tile_gemm64<2, 1>(g_Xf, g_Wh + woff, nullptr, nullptr, nullptr,
                      g_Y + (size_t)m * NN * H, blockIdx.x * 64);
}

// self GEMM: grid 512; Z = X @ self_W^T + self_b, 2-chain, fp32 out
__global__ __launch_bounds__(256, 2) void mma_self_kernel(const float* __restrict__ selfb,
                                                          int l) {
    size_t woff = (size_t)(1 + l * (RREL + 1) + RREL) * H * H;
    tile_gemm64<0, 2>(g_Xf, g_Wh + woff, g_Wl + woff, selfb, g_Z, nullptr,
                      blockIdx.x * 64);
}

// ---------------- edge aggregation: Z[dst] += Y[type][src] / max(deg[dst],1) ----------
__global__ __launch_bounds__(256) void agg_kernel(const int* __restrict__ eidx,
                                                  const int* __restrict__ etype) {
    int e = (blockIdx.x * 256 + threadIdx.x) >> 5;
    int lane = threadIdx.x & 31;
    if (e >= EDGES) return;
    int src = __ldg(eidx + e);
    int dst = __ldg(eidx + EDGES + e);
    int r = __ldg(etype + e);
    float inv = 1.0f / fmaxf(__ldg(&g_deg[dst]), 1.0f);
    const uint2* yrow = (const uint2*)(g_Y + ((size_t)r * NN + src) * H);
    uint2 u = __ldg(yrow + lane);
    __half2 h0 = *(__half2*)&u.x;
    __half2 h1 = *(__half2*)&u.y;
    float2 f0 = __half22float2(h0);
    float2 f1 = __half22float2(h1);
    float4 v;
    v.x = f0.x * inv; v.y = f0.y * inv; v.z = f1.x * inv; v.w = f1.y * inv;
    atomicAdd(((float4*)(g_Z + (size_t)dst * H)) + lane, v);
}

// ---------------- relu passes ----------------
__global__ __launch_bounds__(256) void relu_f16_kernel() {
    int t = blockIdx.x * 256 + threadIdx.x;
    float4 z = ((const float4*)g_Z)[t];
    __half h[4];
    h[0] = __float2half(SCALE * fmaxf(z.x, 0.0f));
    h[1] = __float2half(SCALE * fmaxf(z.y, 0.0f));
    h[2] = __float2half(SCALE * fmaxf(z.z, 0.0f));
    h[3] = __float2half(SCALE * fmaxf(z.w, 0.0f));
    ((uint2*)g_Xf)[t] = *(const uint2*)h;
}

__global__ __launch_bounds__(256) void relu_out_kernel(float* __restrict__ out,
                                                       const int* __restrict__ mask) {
    int t = blockIdx.x * 256 + threadIdx.x;
    int node = t >> 5;
    float m = (float)__ldg(mask + node);
    float4 z = ((const float4*)g_Z)[t];
    float4 v;
    v.x = fmaxf(z.x, 0.0f) * m; v.y = fmaxf(z.y, 0.0f) * m;
    v.z = fmaxf(z.z, 0.0f) * m; v.w = fmaxf(z.w, 0.0f) * m;
    ((float4*)out)[t] = v;
}

// ---------------- launch ----------------
extern "C" void kernel_launch(void* const* d_in, const int* in_sizes, int n_in,
                              void* d_out, int out_size) {
    const int* cid     = (const int*)d_in[0];
    const int* kid     = (const int*)d_in[1];
    const int* mask    = (const int*)d_in[2];
    const int* eidx    = (const int*)d_in[3];
    const int* etype   = (const int*)d_in[4];
    const float* cemb  = (const float*)d_in[5];
    const float* kemb  = (const float*)d_in[6];
    const float* projW = (const float*)d_in[7];
    const float* projb = (const float*)d_in[8];
    const float* selfW = (const float*)d_in[9];
    const float* selfb = (const float*)d_in[10];
    const float* relW  = (const float*)d_in[11];
    float* out = (float*)d_out;

    cudaFuncSetAttribute(mma_proj_kernel, cudaFuncAttributeMaxDynamicSharedMemorySize, SM2_BYTES);
    cudaFuncSetAttribute(mma_rel_kernel, cudaFuncAttributeMaxDynamicSharedMemorySize, SM1_BYTES);
    cudaFuncSetAttribute(mma_self_kernel, cudaFuncAttributeMaxDynamicSharedMemorySize, SM2_BYTES);

    embed_kernel<<<(NN * 32) / 256, 256>>>(cid, kid, cemb, kemb);
    deg_kernel<<<EDGES / 256, 256>>>(eidx);
    convert_w_all_kernel<<<(NMAT * H * H / 8 + 255) / 256, 256>>>(projW, selfW, relW);
    mma_proj_kernel<<<NN / 64, 256, SM2_BYTES>>>(projb);

    for (int l = 0; l < NLAYERS; l++) {
        mma_rel_kernel<<<dim3(NN / 64, RREL), 256, SM1_BYTES>>>(l);
        mma_self_kernel<<<NN / 64, 256, SM2_BYTES>>>(selfb + l * H, l);
        agg_kernel<<<EDGES / 8, 256>>>(eidx, etype);
        if (l == 0)
            relu_f16_kernel<<<(NN * 32) / 256, 256>>>();
        else
            relu_out_kernel<<<(NN * 32) / 256, 256>>>(out, mask);
    }
}

// round 12
// speedup vs baseline: 1.0175x; 1.0175x over previous
#include <cuda_runtime.h>
#include <cuda_fp16.h>
#include <cstdint>
#include <cstddef>

// Problem constants
#define BB 8
#define NSEQ 4096
#define NN 32768            // BB*NSEQ nodes
#define H 128
#define EDGES 524288
#define RREL 8
#define NLAYERS 2

#define PITCH_W 136         // fp16 elems per W smem row (272B)
#define PITCH_A 40          // fp16 elems per A-chunk smem row (80B; 32 data + 8 pad)

// ---- smem map for proj/self streaming kernel (fp16 element offsets) ----
#define SW_H   0
#define SW_L   (128 * PITCH_W)                 // 17408
#define SA_OFF (2 * 128 * PITCH_W)             // 34816
#define SA_SZ  (128 * PITCH_A)                 // 5120 per buffer
#define SM_ELEMS (SA_OFF + 2 * SA_SZ)          // 45056 fp16 = 90112 B

// ---- smem map for persistent relation kernel ----
#define RP_A0  0                               // A buf 0: 128*PITCH_W
#define RP_A1  (128 * PITCH_W)                 // A buf 1
#define RP_W   (2 * 128 * PITCH_W)             // W (resident)
#define RP_SM_BYTES (3 * 128 * PITCH_W * 2)    // 104448 B
#define REL_GRID_X 37                          // 37*8 = 296 CTAs = 2/SM, one wave
#define M_TILES (NN / 128)                     // 256

#define NMAT (1 + NLAYERS * (RREL + 1))        // 19 weight matrices
#define SCALE 64.0f
#define INV_SCALE2 (1.0f / 4096.0f)

// ---------------- scratch (static device globals; no allocation) ----------------
__device__ float g_Z[(size_t)NN * H];            // self-GEMM out / agg accumulator (16 MB)
__device__ __half g_Y[(size_t)RREL * NN * H];    // per-relation messages, fp16 (64 MB)
__device__ __half g_Xf[(size_t)NN * H];          // node states, fp16 scaled x64 (8 MB)
__device__ __half g_Wh[(size_t)NMAT * H * H];    // weight hi splits (x64)
__device__ __half g_Wl[(size_t)NMAT * H * H];    // weight lo splits
__device__ float g_deg[NN];

// ---------------- helpers ----------------
__device__ __forceinline__ uint32_t smem_u32(const void* p) {
    uint32_t a;
    asm("{ .reg .u64 t; cvta.to.shared.u64 t, %1; cvt.u32.u64 %0, t; }" : "=r"(a) : "l"(p));
    return a;
}
__device__ __forceinline__ void cp_async16(uint32_t dst, const void* src) {
    asm volatile("cp.async.cg.shared.global [%0], [%1], 16;" :: "r"(dst), "l"(src));
}
__device__ __forceinline__ void cp_commit() {
    asm volatile("cp.async.commit_group;");
}
__device__ __forceinline__ void cp_wait0() {
    asm volatile("cp.async.wait_group 0;");
}
__device__ __forceinline__ void ldm_x4(uint32_t& r0, uint32_t& r1, uint32_t& r2, uint32_t& r3,
                                       uint32_t addr) {
    asm volatile("ldmatrix.sync.aligned.m8n8.x4.shared.b16 {%0,%1,%2,%3}, [%4];"
                 : "=r"(r0), "=r"(r1), "=r"(r2), "=r"(r3) : "r"(addr));
}
__device__ __forceinline__ void mma16816(float* d, const uint32_t* a, uint32_t b0, uint32_t b1) {
    asm volatile(
        "mma.sync.aligned.m16n8k16.row.col.f32.f16.f16.f32 "
        "{%0,%1,%2,%3}, {%4,%5,%6,%7}, {%8,%9}, {%0,%1,%2,%3};"
        : "+f"(d[0]), "+f"(d[1]), "+f"(d[2]), "+f"(d[3])
        : "r"(a[0]), "r"(a[1]), "r"(a[2]), "r"(a[3]), "r"(b0), "r"(b1));
}
__device__ __forceinline__ void split_h16(float v, __half& hi, __half& lo) {
    hi = __float2half(v);
    lo = __float2half(v - __half2float(hi));
}

// ---------------- embed: Xf = fp16(64*(concept_emb[cid]+kind_emb[kid])); zero deg ------
__global__ __launch_bounds__(256) void embed_kernel(const int* __restrict__ cid,
                                                    const int* __restrict__ kid,
                                                    const float* __restrict__ cemb,
                                                    const float* __restrict__ kemb) {
    int t = blockIdx.x * 256 + threadIdx.x;        // one float4 per thread
    if (t < NN) g_deg[t] = 0.0f;
    int node = t >> 5;
    int q = t & 31;
    int c = __ldg(cid + node);
    int k = __ldg(kid + node);
    float4 a = __ldg(((const float4*)(cemb + (size_t)c * H)) + q);
    float4 b = __ldg(((const float4*)(kemb + (size_t)k * H)) + q);
    __half h[4];
    h[0] = __float2half(SCALE * (a.x + b.x));
    h[1] = __float2half(SCALE * (a.y + b.y));
    h[2] = __float2half(SCALE * (a.z + b.z));
    h[3] = __float2half(SCALE * (a.w + b.w));
    ((uint2*)g_Xf)[t] = *(const uint2*)h;
}

// ---------------- degree ----------------
__global__ __launch_bounds__(256) void deg_kernel(const int* __restrict__ eidx) {
    int e = blockIdx.x * 256 + threadIdx.x;
    if (e < EDGES) atomicAdd(&g_deg[__ldg(eidx + EDGES + e)], 1.0f);
}

// ---------------- all-weight split conversion (proj + both layers, one launch) --------
// layout: [proj][L0: rel0..7, self][L1: rel0..7, self], each 16384 elems
__global__ __launch_bounds__(256) void convert_w_all_kernel(const float* __restrict__ projW,
                                                            const float* __restrict__ selfW,
                                                            const float* __restrict__ relW) {
    int t = blockIdx.x * 256 + threadIdx.x;
    int f8 = t * 8;
    if (f8 >= NMAT * H * H) return;
    const float* src;
    if (f8 < H * H) {
        src = projW + f8;
    } else {
        int g = f8 - H * H;
        int l = g / ((RREL + 1) * H * H);
        int r = g % ((RREL + 1) * H * H);
        if (r < RREL * H * H) src = relW + (size_t)l * RREL * H * H + r;
        else src = selfW + (size_t)l * H * H + (r - RREL * H * H);
    }
    float4 a = *(const float4*)src;
    float4 b = *(const float4*)(src + 4);
    float v[8] = {a.x, a.y, a.z, a.w, b.x, b.y, b.z, b.w};
    __half hi[8], lo[8];
#pragma unroll
    for (int i = 0; i < 8; i++) split_h16(SCALE * v[i], hi[i], lo[i]);
    ((uint4*)g_Wh)[t] = *(const uint4*)hi;
    ((uint4*)g_Wl)[t] = *(const uint4*)lo;
}

// ---------------- 128x128x128 fp16 HMMA tile GEMM (R9-verified streaming version) -----
// O[m][g] = sum_k A[m][k]*W[g][k] (scaled ops; /4096 + bias in epilogue).
// W resident in smem; A streamed in 4 k-chunks of 32 with cp.async double buffer.
// OUT_MODE 0: fp32 -> O (+bias).  OUT_MODE 1: fp16 x64 -> Oh (+bias; in place over A ok).
template <int OUT_MODE, int CHAINS>
__device__ __forceinline__ void tile_gemm(const __half* __restrict__ A_g,
                                          const __half* __restrict__ Wh_g,
                                          const __half* __restrict__ Wl_g,
                                          const float* __restrict__ bias,
                                          float* __restrict__ O,
                                          __half* __restrict__ Oh, int m0) {
    extern __shared__ __half sm[];
    const uint32_t sbase = smem_u32(sm);
    const int tid = threadIdx.x;
    const __half* Ag = A_g + (size_t)m0 * H;

    {
        const __half* wsrc[2] = {Wh_g, Wl_g};
#pragma unroll
        for (int hl = 0; hl < CHAINS; hl++) {
#pragma unroll
            for (int it = 0; it < 8; it++) {
                int i = tid + it * 256;       // 0..2047 uint4 chunks (16 per row)
                int r = i >> 4;
                int c = i & 15;
                uint32_t dst = sbase + ((hl ? SW_L : SW_H) + r * PITCH_W + c * 8) * 2;
                cp_async16(dst, wsrc[hl] + r * H + c * 8);
            }
        }
#pragma unroll
        for (int it = 0; it < 2; it++) {
            int i = tid + it * 256;           // 0..511
            int r = i >> 2;
            int c = i & 3;
            uint32_t dst = sbase + (SA_OFF + r * PITCH_A + c * 8) * 2;
            cp_async16(dst, Ag + r * H + c * 8);
        }
        cp_commit();
        cp_wait0();
    }
    __syncthreads();

    const int wid = tid >> 5;
    const int lane = tid & 31;
    const int wm = wid >> 2;
    const int wn = wid & 3;

    float acc[4][4][4];
#pragma unroll
    for (int i = 0; i < 4; i++)
#pragma unroll
        for (int j = 0; j < 4; j++)
#pragma unroll
            for (int k = 0; k < 4; k++) acc[i][j][k] = 0.0f;

    const uint32_t lrow = lane & 15;
    const uint32_t lhalf = lane >> 4;
    const uint32_t aWh = sbase + (SW_H + (wn * 32 + lrow) * PITCH_W + lhalf * 8) * 2;
    const uint32_t aWl = sbase + (SW_L + (wn * 32 + lrow) * PITCH_W + lhalf * 8) * 2;
    const uint32_t aA0 = sbase + (SA_OFF + (wm * 64 + lrow) * PITCH_A + lhalf * 8) * 2;

#pragma unroll
    for (int kc = 0; kc < 4; kc++) {
        if (kc < 3) {
            int b = (kc + 1) & 1;
#pragma unroll
            for (int it = 0; it < 2; it++) {
                int i = tid + it * 256;
                int r = i >> 2;
                int c = i & 3;
                uint32_t dst = sbase + (SA_OFF + b * SA_SZ + r * PITCH_A + c * 8) * 2;
                cp_async16(dst, Ag + r * H + (kc + 1) * 32 + c * 8);
            }
            cp_commit();
        }
        const uint32_t aA = aA0 + (kc & 1) * (SA_SZ * 2);
#pragma unroll
        for (int kstep = 0; kstep < 2; kstep++) {
            const int ks = kc * 2 + kstep;
            const uint32_t wkoff = ks * 32;
            const uint32_t akoff = kstep * 32;
            uint32_t bh[2][4], bl[2][4];
#pragma unroll
            for (int bi = 0; bi < 2; bi++) {
                ldm_x4(bh[bi][0], bh[bi][1], bh[bi][2], bh[bi][3],
                       aWh + bi * (16 * PITCH_W * 2) + wkoff);
                if (CHAINS == 2) {
                    ldm_x4(bl[bi][0], bl[bi][1], bl[bi][2], bl[bi][3],
                           aWl + bi * (16 * PITCH_W * 2) + wkoff);
                }
            }
#pragma unroll
            for (int mi = 0; mi < 4; mi++) {
                uint32_t a[4];
                ldm_x4(a[0], a[1], a[2], a[3], aA + mi * (16 * PITCH_A * 2) + akoff);
#pragma unroll
                for (int bi = 0; bi < 2; bi++) {
                    mma16816(acc[mi][2 * bi + 0], a, bh[bi][0], bh[bi][2]);
                    mma16816(acc[mi][2 * bi + 1], a, bh[bi][1], bh[bi][3]);
                    if (CHAINS == 2) {
                        mma16816(acc[mi][2 * bi + 0], a, bl[bi][0], bl[bi][2]);
                        mma16816(acc[mi][2 * bi + 1], a, bl[bi][1], bl[bi][3]);
                    }
                }
            }
        }
        if (kc < 3) {
            cp_wait0();
            __syncthreads();
        }
    }

    const int gID = lane >> 2;
    const int tig = lane & 3;
#pragma unroll
    for (int mi = 0; mi < 4; mi++) {
#pragma unroll
        for (int nt = 0; nt < 4; nt++) {
            int col = wn * 32 + nt * 8 + tig * 2;
            float b0 = 0.0f, b1 = 0.0f;
            if (bias) { b0 = __ldg(bias + col); b1 = __ldg(bias + col + 1); }
#pragma unroll
            for (int half = 0; half < 2; half++) {
                int row = m0 + wm * 64 + mi * 16 + gID + half * 8;
                float v0 = acc[mi][nt][2 * half + 0] * INV_SCALE2 + b0;
                float v1 = acc[mi][nt][2 * half + 1] * INV_SCALE2 + b1;
                if (OUT_MODE == 0) {
                    float2 fv = make_float2(v0, v1);
                    *(float2*)(O + (size_t)row * H + col) = fv;
                } else {
                    __half2 hv;
                    hv.x = __float2half(SCALE * v0);
                    hv.y = __float2half(SCALE * v1);
                    *(__half2*)(Oh + (size_t)row * H + col) = hv;
                }
            }
        }
    }
}

// proj: Xf = fp16 x64 of (E0 @ projW^T + projb), in-place over Xf (2-chain)
__global__ __launch_bounds__(256, 2) void mma_proj_kernel(const float* __restrict__ projb) {
    tile_gemm<1, 2>(g_Xf, g_Wh, g_Wl, projb, nullptr, g_Xf, blockIdx.x * 128);
}

// self GEMM: Z = X @ self_W^T + self_b (2-chain, fp32 out)
__global__ __launch_bounds__(256, 2) void mma_self_kernel(const float* __restrict__ selfb,
                                                          int l) {
    size_t woff = (size_t)(1 + l * (RREL + 1) + RREL) * H * H;
    tile_gemm<0, 2>(g_Xf, g_Wh + woff, g_Wl + woff, selfb, g_Z, nullptr, blockIdx.x * 128);
}

// ---------------- persistent relation GEMM: W resident, m-tiles streamed --------------
// grid (37, 8): CTA owns relation blockIdx.y; loops m-tiles t = bx, bx+37, ... < 256.
// Per tile: Y[r][t*128 .. t*128+127] = Xf_tile @ W_r^T (1-chain, fp16 unscaled out).
// A double-buffered (full 128x128 tile per buffer) via cp.async, prefetch overlapped.
__global__ __launch_bounds__(256, 2) void mma_rel_persist_kernel(int l) {
    extern __shared__ __half sm[];
    const uint32_t sbase = smem_u32(sm);
    const int tid = threadIdx.x;
    const int r = blockIdx.y;
    const __half* Wg = g_Wh + (size_t)(1 + l * (RREL + 1) + r) * H * H;
    __half* Yr = g_Y + (size_t)r * NN * H;

    // prologue: W (resident) + A tile0 into buf0
    {
        const int t0 = blockIdx.x;
        const __half* Ag = g_Xf + (size_t)t0 * 128 * H;
#pragma unroll
        for (int it = 0; it < 8; it++) {
            int i = tid + it * 256;           // 0..2047, 16 chunks per row
            int rr = i >> 4;
            int c = i & 15;
            cp_async16(sbase + (RP_W + rr * PITCH_W + c * 8) * 2, Wg + rr * H + c * 8);
        }
#pragma unroll
        for (int it = 0; it < 8; it++) {
            int i = tid + it * 256;
            int rr = i >> 4;
            int c = i & 15;
            cp_async16(sbase + (RP_A0 + rr * PITCH_W + c * 8) * 2,
                       Ag + rr * H + c * 8);
        }
        cp_commit();
        cp_wait0();
    }
    __syncthreads();

    const int wid = tid >> 5;
    const int lane = tid & 31;
    const int wm = wid >> 2;       // 0..1 : 64-row block
    const int wn = wid & 3;        // 0..3 : 32-col block
    const uint32_t lrow = lane & 15;
    const uint32_t lhalf = lane >> 4;
    const uint32_t aW = sbase + (RP_W + (wn * 32 + lrow) * PITCH_W + lhalf * 8) * 2;
    const uint32_t aAb[2] = {
        sbase + (RP_A0 + (wm * 64 + lrow) * PITCH_W + lhalf * 8) * 2,
        sbase + (RP_A1 + (wm * 64 + lrow) * PITCH_W + lhalf * 8) * 2};
    const int gID = lane >> 2;
    const int tig = lane & 3;

    int buf = 0;
#pragma unroll 1
    for (int t = blockIdx.x; t < M_TILES; t += REL_GRID_X) {
        const int tn = t + REL_GRID_X;
        // prefetch next A tile into other buffer (overlapped with compute)
        if (tn < M_TILES) {
            const __half* Agn = g_Xf + (size_t)tn * 128 * H;
            const uint32_t adst = sbase + ((buf ^ 1) ? RP_A1 : RP_A0) * 2;
#pragma unroll
            for (int it = 0; it < 8; it++) {
                int i = tid + it * 256;
                int rr = i >> 4;
                int c = i & 15;
                cp_async16(adst + (rr * PITCH_W + c * 8) * 2, Agn + rr * H + c * 8);
            }
            cp_commit();
        }

        float acc[4][4][4];
#pragma unroll
        for (int i = 0; i < 4; i++)
#pragma unroll
            for (int j = 0; j < 4; j++)
#pragma unroll
                for (int k = 0; k < 4; k++) acc[i][j][k] = 0.0f;

        const uint32_t aA = aAb[buf];
#pragma unroll
        for (int ks = 0; ks < 8; ks++) {
            const uint32_t koff = ks * 32;
            uint32_t bh[2][4];
#pragma unroll
            for (int bi = 0; bi < 2; bi++) {
                ldm_x4(bh[bi][0], bh[bi][1], bh[bi][2], bh[bi][3],
                       aW + bi * (16 * PITCH_W * 2) + koff);
            }
#pragma unroll
            for (int mi = 0; mi < 4; mi++) {
                uint32_t a[4];
                ldm_x4(a[0], a[1], a[2], a[3], aA + mi * (16 * PITCH_W * 2) + koff);
#pragma unroll
                for (int bi = 0; bi < 2; bi++) {
                    mma16816(acc[mi][2 * bi + 0], a, bh[bi][0], bh[bi][2]);
                    mma16816(acc[mi][2 * bi + 1], a, bh[bi][1], bh[bi][3]);
                }
            }
        }

        // epilogue: Y fp16 unscaled
        const int m0 = t * 128;
#pragma unroll
        for (int mi = 0; mi < 4; mi++) {
#pragma unroll
            for (int nt = 0; nt < 4; nt++) {
                int col = wn * 32 + nt * 8 + tig * 2;
#pragma unroll
                for (int half = 0; half < 2; half++) {
                    int row = m0 + wm * 64 + mi * 16 + gID + half * 8;
                    __half2 hv;
                    hv.x = __float2half(acc[mi][nt][2 * half + 0] * INV_SCALE2);
                    hv.y = __float2half(acc[mi][nt][2 * half + 1] * INV_SCALE2);
                    *(__half2*)(Yr + (size_t)row * H + col) = hv;
                }
            }
        }

        if (tn < M_TILES) {
            cp_wait0();
            __syncthreads();
            buf ^= 1;
        }
    }
}

// ---------------- edge aggregation: Z[dst] += Y[type][src] / max(deg[dst],1) ----------
__global__ __launch_bounds__(256) void agg_kernel(const int* __restrict__ eidx,
                                                  const int* __restrict__ etype) {
    int e = (blockIdx.x * 256 + threadIdx.x) >> 5;
    int lane = threadIdx.x & 31;
    if (e >= EDGES) return;
    int src = __ldg(eidx + e);
    int dst = __ldg(eidx + EDGES + e);
    int r = __ldg(etype + e);
    float inv = 1.0f / fmaxf(__ldg(&g_deg[dst]), 1.0f);
    const uint2* yrow = (const uint2*)(g_Y + ((size_t)r * NN + src) * H);
    uint2 u = __ldg(yrow + lane);
    __half2 h0 = *(__half2*)&u.x;
    __half2 h1 = *(__half2*)&u.y;
    float2 f0 = __half22float2(h0);
    float2 f1 = __half22float2(h1);
    float4 v;
    v.x = f0.x * inv; v.y = f0.y * inv; v.z = f1.x * inv; v.w = f1.y * inv;
    atomicAdd(((float4*)(g_Z + (size_t)dst * H)) + lane, v);
}

// ---------------- relu passes ----------------
__global__ __launch_bounds__(256) void relu_f16_kernel() {
    int t = blockIdx.x * 256 + threadIdx.x;
    float4 z = ((const float4*)g_Z)[t];
    __half h[4];
    h[0] = __float2half(SCALE * fmaxf(z.x, 0.0f));
    h[1] = __float2half(SCALE * fmaxf(z.y, 0.0f));
    h[2] = __float2half(SCALE * fmaxf(z.z, 0.0f));
    h[3] = __float2half(SCALE * fmaxf(z.w, 0.0f));
    ((uint2*)g_Xf)[t] = *(const uint2*)h;
}

__global__ __launch_bounds__(256) void relu_out_kernel(float* __restrict__ out,
                                                       const int* __restrict__ mask) {
    int t = blockIdx.x * 256 + threadIdx.x;
    int node = t >> 5;
    float m = (float)__ldg(mask + node);
    float4 z = ((const float4*)g_Z)[t];
    float4 v;
    v.x = fmaxf(z.x, 0.0f) * m; v.y = fmaxf(z.y, 0.0f) * m;
    v.z = fmaxf(z.z, 0.0f) * m; v.w = fmaxf(z.w, 0.0f) * m;
    ((float4*)out)[t] = v;
}

// ---------------- launch ----------------
extern "C" void kernel_launch(void* const* d_in, const int* in_sizes, int n_in,
                              void* d_out, int out_size) {
    const int* cid     = (const int*)d_in[0];
    const int* kid     = (const int*)d_in[1];
    const int* mask    = (const int*)d_in[2];
    const int* eidx    = (const int*)d_in[3];
    const int* etype   = (const int*)d_in[4];
    const float* cemb  = (const float*)d_in[5];
    const float* kemb  = (const float*)d_in[6];
    const float* projW = (const float*)d_in[7];
    const float* projb = (const float*)d_in[8];
    const float* selfW = (const float*)d_in[9];
    const float* selfb = (const float*)d_in[10];
    const float* relW  = (const float*)d_in[11];
    float* out = (float*)d_out;

    const int stream_smem = SM_ELEMS * 2;    // 90112
    cudaFuncSetAttribute(mma_proj_kernel, cudaFuncAttributeMaxDynamicSharedMemorySize,
                         stream_smem);
    cudaFuncSetAttribute(mma_self_kernel, cudaFuncAttributeMaxDynamicSharedMemorySize,
                         stream_smem);
    cudaFuncSetAttribute(mma_rel_persist_kernel, cudaFuncAttributeMaxDynamicSharedMemorySize,
                         RP_SM_BYTES);

    embed_kernel<<<(NN * 32) / 256, 256>>>(cid, kid, cemb, kemb);
    deg_kernel<<<EDGES / 256, 256>>>(eidx);
    convert_w_all_kernel<<<(NMAT * H * H / 8 + 255) / 256, 256>>>(projW, selfW, relW);
    mma_proj_kernel<<<NN / 128, 256, stream_smem>>>(projb);

    for (int l = 0; l < NLAYERS; l++) {
        mma_rel_persist_kernel<<<dim3(REL_GRID_X, RREL), 256, RP_SM_BYTES>>>(l);
        mma_self_kernel<<<NN / 128, 256, stream_smem>>>(selfb + l * H, l);
        agg_kernel<<<EDGES / 8, 256>>>(eidx, etype);
        if (l == 0)
            relu_f16_kernel<<<(NN * 32) / 256, 256>>>();
        else
            relu_out_kernel<<<(NN * 32) / 256, 256>>>(out, mask);
    }
}

// round 13
// speedup vs baseline: 1.1827x; 1.1624x over previous
#include <cuda_runtime.h>
#include <cuda_fp16.h>
#include <cstdint>
#include <cstddef>

// Problem constants
#define BB 8
#define NSEQ 4096
#define NN 32768            // BB*NSEQ nodes
#define H 128
#define EDGES 524288
#define RREL 8
#define NLAYERS 2

#define PITCH_W 136         // fp16 elems per W smem row (272B)
#define PITCH_A 40          // fp16 elems per A-chunk smem row (80B; 32 data + 8 pad)

// ---- smem map for streaming GEMM kernels (fp16 element offsets) ----
#define SW_H   0
#define SW_L   (128 * PITCH_W)                 // 17408
#define SA_OFF (2 * 128 * PITCH_W)             // 34816
#define SA_SZ  (128 * PITCH_A)                 // 5120 per buffer
#define SM_ELEMS (SA_OFF + 2 * SA_SZ)          // 45056 fp16 = 90112 B

#define NMAT (1 + NLAYERS * (RREL + 1))        // 19 weight matrices
#define SCALE 64.0f
#define INV_SCALE2 (1.0f / 4096.0f)

// ---------------- scratch (static device globals; no allocation) ----------------
__device__ float g_Z[(size_t)NN * H];            // self-GEMM out / agg base (16 MB)
__device__ __half g_Y[(size_t)RREL * NN * H];    // per-relation messages, fp16 (64 MB)
__device__ __half g_Xf[(size_t)NN * H];          // node states, fp16 scaled x64 (8 MB)
__device__ __half g_Wh[(size_t)NMAT * H * H];    // weight hi splits (x64)
__device__ __half g_Wl[(size_t)NMAT * H * H];    // weight lo splits
__device__ int g_degi[NN];                       // in-degree (int)
__device__ int g_off[NN];                        // CSR offsets (exclusive prefix of degi)
__device__ int g_cursor[NN];                     // scatter cursors
__device__ int g_epack[EDGES];                   // dst-bucketed packed edges: src | (r<<15)

// ---------------- helpers ----------------
__device__ __forceinline__ uint32_t smem_u32(const void* p) {
    uint32_t a;
    asm("{ .reg .u64 t; cvta.to.shared.u64 t, %1; cvt.u32.u64 %0, t; }" : "=r"(a) : "l"(p));
    return a;
}
__device__ __forceinline__ void cp_async16(uint32_t dst, const void* src) {
    asm volatile("cp.async.cg.shared.global [%0], [%1], 16;" :: "r"(dst), "l"(src));
}
__device__ __forceinline__ void cp_commit() {
    asm volatile("cp.async.commit_group;");
}
__device__ __forceinline__ void cp_wait0() {
    asm volatile("cp.async.wait_group 0;");
}
__device__ __forceinline__ void ldm_x4(uint32_t& r0, uint32_t& r1, uint32_t& r2, uint32_t& r3,
                                       uint32_t addr) {
    asm volatile("ldmatrix.sync.aligned.m8n8.x4.shared.b16 {%0,%1,%2,%3}, [%4];"
                 : "=r"(r0), "=r"(r1), "=r"(r2), "=r"(r3) : "r"(addr));
}
__device__ __forceinline__ void mma16816(float* d, const uint32_t* a, uint32_t b0, uint32_t b1) {
    asm volatile(
        "mma.sync.aligned.m16n8k16.row.col.f32.f16.f16.f32 "
        "{%0,%1,%2,%3}, {%4,%5,%6,%7}, {%8,%9}, {%0,%1,%2,%3};"
        : "+f"(d[0]), "+f"(d[1]), "+f"(d[2]), "+f"(d[3])
        : "r"(a[0]), "r"(a[1]), "r"(a[2]), "r"(a[3]), "r"(b0), "r"(b1));
}
__device__ __forceinline__ void split_h16(float v, __half& hi, __half& lo) {
    hi = __float2half(v);
    lo = __float2half(v - __half2float(hi));
}

// ---------------- embed: Xf = fp16(64*(concept_emb[cid]+kind_emb[kid])); zero degi -----
__global__ __launch_bounds__(256) void embed_kernel(const int* __restrict__ cid,
                                                    const int* __restrict__ kid,
                                                    const float* __restrict__ cemb,
                                                    const float* __restrict__ kemb) {
    int t = blockIdx.x * 256 + threadIdx.x;        // one float4 per thread
    if (t < NN) g_degi[t] = 0;
    int node = t >> 5;
    int q = t & 31;
    int c = __ldg(cid + node);
    int k = __ldg(kid + node);
    float4 a = __ldg(((const float4*)(cemb + (size_t)c * H)) + q);
    float4 b = __ldg(((const float4*)(kemb + (size_t)k * H)) + q);
    __half h[4];
    h[0] = __float2half(SCALE * (a.x + b.x));
    h[1] = __float2half(SCALE * (a.y + b.y));
    h[2] = __float2half(SCALE * (a.z + b.z));
    h[3] = __float2half(SCALE * (a.w + b.w));
    ((uint2*)g_Xf)[t] = *(const uint2*)h;
}

// ---------------- degree (int) ----------------
__global__ __launch_bounds__(256) void deg_kernel(const int* __restrict__ eidx) {
    int e = blockIdx.x * 256 + threadIdx.x;
    if (e < EDGES) atomicAdd(&g_degi[__ldg(eidx + EDGES + e)], 1);
}

// ---------------- single-CTA scan: off/cursor = exclusive prefix of degi ----------------
__global__ __launch_bounds__(1024) void scan_kernel() {
    __shared__ int s[1024];
    int tid = threadIdx.x;
    int base = tid * 32;
    int v[32];
    int sum = 0;
#pragma unroll
    for (int i = 0; i < 32; i++) { v[i] = g_degi[base + i]; sum += v[i]; }
    s[tid] = sum;
    __syncthreads();
    for (int off = 1; off < 1024; off <<= 1) {
        int t = (tid >= off) ? s[tid - off] : 0;
        __syncthreads();
        s[tid] += t;
        __syncthreads();
    }
    int run = s[tid] - sum;   // exclusive prefix of this thread's chunk
#pragma unroll
    for (int i = 0; i < 32; i++) {
        g_off[base + i] = run;
        g_cursor[base + i] = run;
        run += v[i];
    }
}

// ---------------- scatter: bucket edges by dst, packed src | (r<<15) ----------------
__global__ __launch_bounds__(256) void scatter_kernel(const int* __restrict__ eidx,
                                                      const int* __restrict__ etype) {
    int e = blockIdx.x * 256 + threadIdx.x;
    if (e >= EDGES) return;
    int src = __ldg(eidx + e);
    int dst = __ldg(eidx + EDGES + e);
    int r = __ldg(etype + e);
    int pos = atomicAdd(&g_cursor[dst], 1);
    g_epack[pos] = src | (r << 15);
}

// ---------------- all-weight split conversion (proj + both layers, one launch) --------
__global__ __launch_bounds__(256) void convert_w_all_kernel(const float* __restrict__ projW,
                                                            const float* __restrict__ selfW,
                                                            const float* __restrict__ relW) {
    int t = blockIdx.x * 256 + threadIdx.x;
    int f8 = t * 8;
    if (f8 >= NMAT * H * H) return;
    const float* src;
    if (f8 < H * H) {
        src = projW + f8;
    } else {
        int g = f8 - H * H;
        int l = g / ((RREL + 1) * H * H);
        int r = g % ((RREL + 1) * H * H);
        if (r < RREL * H * H) src = relW + (size_t)l * RREL * H * H + r;
        else src = selfW + (size_t)l * H * H + (r - RREL * H * H);
    }
    float4 a = *(const float4*)src;
    float4 b = *(const float4*)(src + 4);
    float v[8] = {a.x, a.y, a.z, a.w, b.x, b.y, b.z, b.w};
    __half hi[8], lo[8];
#pragma unroll
    for (int i = 0; i < 8; i++) split_h16(SCALE * v[i], hi[i], lo[i]);
    ((uint4*)g_Wh)[t] = *(const uint4*)hi;
    ((uint4*)g_Wl)[t] = *(const uint4*)lo;
}

// ---------------- 128x128x128 fp16 HMMA tile GEMM (R9-verified streaming) ----------------
// O[m][g] = sum_k A[m][k]*W[g][k] (scaled ops; /4096 + bias in epilogue).
// OUT_MODE 0: fp32 -> O (+bias).  OUT_MODE 1: fp16 x64 -> Oh (+bias).  OUT_MODE 2: fp16 raw.
template <int OUT_MODE, int CHAINS>
__device__ __forceinline__ void tile_gemm(const __half* __restrict__ A_g,
                                          const __half* __restrict__ Wh_g,
                                          const __half* __restrict__ Wl_g,
                                          const float* __restrict__ bias,
                                          float* __restrict__ O,
                                          __half* __restrict__ Oh, int m0) {
    extern __shared__ __half sm[];
    const uint32_t sbase = smem_u32(sm);
    const int tid = threadIdx.x;
    const __half* Ag = A_g + (size_t)m0 * H;

    {
        const __half* wsrc[2] = {Wh_g, Wl_g};
#pragma unroll
        for (int hl = 0; hl < CHAINS; hl++) {
#pragma unroll
            for (int it = 0; it < 8; it++) {
                int i = tid + it * 256;
                int r = i >> 4;
                int c = i & 15;
                uint32_t dst = sbase + ((hl ? SW_L : SW_H) + r * PITCH_W + c * 8) * 2;
                cp_async16(dst, wsrc[hl] + r * H + c * 8);
            }
        }
#pragma unroll
        for (int it = 0; it < 2; it++) {
            int i = tid + it * 256;
            int r = i >> 2;
            int c = i & 3;
            uint32_t dst = sbase + (SA_OFF + r * PITCH_A + c * 8) * 2;
            cp_async16(dst, Ag + r * H + c * 8);
        }
        cp_commit();
        cp_wait0();
    }
    __syncthreads();

    const int wid = tid >> 5;
    const int lane = tid & 31;
    const int wm = wid >> 2;
    const int wn = wid & 3;

    float acc[4][4][4];
#pragma unroll
    for (int i = 0; i < 4; i++)
#pragma unroll
        for (int j = 0; j < 4; j++)
#pragma unroll
            for (int k = 0; k < 4; k++) acc[i][j][k] = 0.0f;

    const uint32_t lrow = lane & 15;
    const uint32_t lhalf = lane >> 4;
    const uint32_t aWh = sbase + (SW_H + (wn * 32 + lrow) * PITCH_W + lhalf * 8) * 2;
    const uint32_t aWl = sbase + (SW_L + (wn * 32 + lrow) * PITCH_W + lhalf * 8) * 2;
    const uint32_t aA0 = sbase + (SA_OFF + (wm * 64 + lrow) * PITCH_A + lhalf * 8) * 2;

#pragma unroll
    for (int kc = 0; kc < 4; kc++) {
        if (kc < 3) {
            int b = (kc + 1) & 1;
#pragma unroll
            for (int it = 0; it < 2; it++) {
                int i = tid + it * 256;
                int r = i >> 2;
                int c = i & 3;
                uint32_t dst = sbase + (SA_OFF + b * SA_SZ + r * PITCH_A + c * 8) * 2;
                cp_async16(dst, Ag + r * H + (kc + 1) * 32 + c * 8);
            }
            cp_commit();
        }
        const uint32_t aA = aA0 + (kc & 1) * (SA_SZ * 2);
#pragma unroll
        for (int kstep = 0; kstep < 2; kstep++) {
            const int ks = kc * 2 + kstep;
            const uint32_t wkoff = ks * 32;
            const uint32_t akoff = kstep * 32;
            uint32_t bh[2][4], bl[2][4];
#pragma unroll
            for (int bi = 0; bi < 2; bi++) {
                ldm_x4(bh[bi][0], bh[bi][1], bh[bi][2], bh[bi][3],
                       aWh + bi * (16 * PITCH_W * 2) + wkoff);
                if (CHAINS == 2) {
                    ldm_x4(bl[bi][0], bl[bi][1], bl[bi][2], bl[bi][3],
                           aWl + bi * (16 * PITCH_W * 2) + wkoff);
                }
            }
#pragma unroll
            for (int mi = 0; mi < 4; mi++) {
                uint32_t a[4];
                ldm_x4(a[0], a[1], a[2], a[3], aA + mi * (16 * PITCH_A * 2) + akoff);
#pragma unroll
                for (int bi = 0; bi < 2; bi++) {
                    mma16816(acc[mi][2 * bi + 0], a, bh[bi][0], bh[bi][2]);
                    mma16816(acc[mi][2 * bi + 1], a, bh[bi][1], bh[bi][3]);
                    if (CHAINS == 2) {
                        mma16816(acc[mi][2 * bi + 0], a, bl[bi][0], bl[bi][2]);
                        mma16816(acc[mi][2 * bi + 1], a, bl[bi][1], bl[bi][3]);
                    }
                }
            }
        }
        if (kc < 3) {
            cp_wait0();
            __syncthreads();
        }
    }

    const int gID = lane >> 2;
    const int tig = lane & 3;
#pragma unroll
    for (int mi = 0; mi < 4; mi++) {
#pragma unroll
        for (int nt = 0; nt < 4; nt++) {
            int col = wn * 32 + nt * 8 + tig * 2;
            float b0 = 0.0f, b1 = 0.0f;
            if (OUT_MODE != 2 && bias) { b0 = __ldg(bias + col); b1 = __ldg(bias + col + 1); }
#pragma unroll
            for (int half = 0; half < 2; half++) {
                int row = m0 + wm * 64 + mi * 16 + gID + half * 8;
                float v0 = acc[mi][nt][2 * half + 0] * INV_SCALE2 + b0;
                float v1 = acc[mi][nt][2 * half + 1] * INV_SCALE2 + b1;
                if (OUT_MODE == 0) {
                    float2 fv = make_float2(v0, v1);
                    *(float2*)(O + (size_t)row * H + col) = fv;
                } else if (OUT_MODE == 1) {
                    __half2 hv;
                    hv.x = __float2half(SCALE * v0);
                    hv.y = __float2half(SCALE * v1);
                    *(__half2*)(Oh + (size_t)row * H + col) = hv;
                } else {
                    __half2 hv;
                    hv.x = __float2half(v0);
                    hv.y = __float2half(v1);
                    *(__half2*)(Oh + (size_t)row * H + col) = hv;
                }
            }
        }
    }
}

// proj: Xf = fp16 x64 of (E0 @ projW^T + projb), in-place over Xf (2-chain)
__global__ __launch_bounds__(256, 2) void mma_proj_kernel(const float* __restrict__ projb) {
    tile_gemm<1, 2>(g_Xf, g_Wh, g_Wl, projb, nullptr, g_Xf, blockIdx.x * 128);
}

// grid.y = 9: m<8 -> Y[m] = X @ rel_W[m]^T (1-chain, fp16 out) ; m==8 -> Z (2-chain, fp32)
__global__ __launch_bounds__(256, 2) void mma_layer_kernel(const float* __restrict__ selfb,
                                                           int l) {
    int m = blockIdx.y;
    size_t woff = (size_t)(1 + l * (RREL + 1) + m) * H * H;
    const __half* wh = g_Wh + woff;
    const __half* wl = g_Wl + woff;
    if (m < RREL) {
        tile_gemm<2, 1>(g_Xf, wh, wl, nullptr, nullptr, g_Y + (size_t)m * NN * H,
                        blockIdx.x * 128);
    } else {
        tile_gemm<0, 2>(g_Xf, wh, wl, selfb, g_Z, nullptr, blockIdx.x * 128);
    }
}

// ---------------- CSR aggregation + fused relu epilogue ----------------
// Warp per dst node: gather its bucketed edges' Y rows, accumulate fp32, add Z row,
// relu, write Xf (layer 0) or masked out (layer 1). No atomics.
__global__ __launch_bounds__(256) void agg_fused_kernel(int layer, float* __restrict__ out,
                                                        const int* __restrict__ mask) {
    int w = (blockIdx.x * 256 + threadIdx.x) >> 5;   // dst node, grid covers exactly NN
    int lane = threadIdx.x & 31;
    int off = __ldg(&g_off[w]);
    int n = __ldg(&g_degi[w]);
    float inv = 1.0f / fmaxf((float)n, 1.0f);
    float4 acc = make_float4(0.0f, 0.0f, 0.0f, 0.0f);

    for (int b = 0; b < n; b += 32) {
        int m = min(32, n - b);
        int pk = (b + lane < n) ? __ldg(g_epack + off + b + lane) : 0;
        int j = 0;
        for (; j + 4 <= m; j += 4) {
            uint2 u[4];
#pragma unroll
            for (int q = 0; q < 4; q++) {
                int p = __shfl_sync(0xffffffffu, pk, j + q);
                const uint2* yrow = (const uint2*)(g_Y +
                    ((size_t)((p >> 15) & 7) * NN + (p & 0x7FFF)) * H);
                u[q] = __ldg(yrow + lane);
            }
#pragma unroll
            for (int q = 0; q < 4; q++) {
                __half2 h0 = *(__half2*)&u[q].x;
                __half2 h1 = *(__half2*)&u[q].y;
                float2 f0 = __half22float2(h0);
                float2 f1 = __half22float2(h1);
                acc.x += f0.x; acc.y += f0.y; acc.z += f1.x; acc.w += f1.y;
            }
        }
        for (; j < m; j++) {
            int p = __shfl_sync(0xffffffffu, pk, j);
            const uint2* yrow = (const uint2*)(g_Y +
                ((size_t)((p >> 15) & 7) * NN + (p & 0x7FFF)) * H);
            uint2 u = __ldg(yrow + lane);
            __half2 h0 = *(__half2*)&u.x;
            __half2 h1 = *(__half2*)&u.y;
            float2 f0 = __half22float2(h0);
            float2 f1 = __half22float2(h1);
            acc.x += f0.x; acc.y += f0.y; acc.z += f1.x; acc.w += f1.y;
        }
    }

    float4 z = *(((const float4*)(g_Z + (size_t)w * H)) + lane);
    float4 v;
    v.x = fmaxf(z.x + acc.x * inv, 0.0f);
    v.y = fmaxf(z.y + acc.y * inv, 0.0f);
    v.z = fmaxf(z.z + acc.z * inv, 0.0f);
    v.w = fmaxf(z.w + acc.w * inv, 0.0f);

    if (layer == 0) {
        __half h[4];
        h[0] = __float2half(SCALE * v.x);
        h[1] = __float2half(SCALE * v.y);
        h[2] = __float2half(SCALE * v.z);
        h[3] = __float2half(SCALE * v.w);
        ((uint2*)g_Xf)[w * 32 + lane] = *(const uint2*)h;
    } else {
        float mk = (float)__ldg(mask + w);
        v.x *= mk; v.y *= mk; v.z *= mk; v.w *= mk;
        ((float4*)out)[w * 32 + lane] = v;
    }
}

// ---------------- launch ----------------
extern "C" void kernel_launch(void* const* d_in, const int* in_sizes, int n_in,
                              void* d_out, int out_size) {
    const int* cid     = (const int*)d_in[0];
    const int* kid     = (const int*)d_in[1];
    const int* mask    = (const int*)d_in[2];
    const int* eidx    = (const int*)d_in[3];
    const int* etype   = (const int*)d_in[4];
    const float* cemb  = (const float*)d_in[5];
    const float* kemb  = (const float*)d_in[6];
    const float* projW = (const float*)d_in[7];
    const float* projb = (const float*)d_in[8];
    const float* selfW = (const float*)d_in[9];
    const float* selfb = (const float*)d_in[10];
    const float* relW  = (const float*)d_in[11];
    float* out = (float*)d_out;

    const int smem_bytes = SM_ELEMS * 2;   // 90112
    cudaFuncSetAttribute(mma_proj_kernel, cudaFuncAttributeMaxDynamicSharedMemorySize, smem_bytes);
    cudaFuncSetAttribute(mma_layer_kernel, cudaFuncAttributeMaxDynamicSharedMemorySize, smem_bytes);

    embed_kernel<<<(NN * 32) / 256, 256>>>(cid, kid, cemb, kemb);   // also zeroes degi
    deg_kernel<<<EDGES / 256, 256>>>(eidx);
    scan_kernel<<<1, 1024>>>();
    scatter_kernel<<<EDGES / 256, 256>>>(eidx, etype);
    convert_w_all_kernel<<<(NMAT * H * H / 8 + 255) / 256, 256>>>(projW, selfW, relW);
    mma_proj_kernel<<<NN / 128, 256, smem_bytes>>>(projb);

    for (int l = 0; l < NLAYERS; l++) {
        mma_layer_kernel<<<dim3(NN / 128, RREL + 1), 256, smem_bytes>>>(selfb + l * H, l);
        agg_fused_kernel<<<(NN * 32) / 256, 256>>>(l, out, mask);
    }
}

// round 14
// speedup vs baseline: 1.2520x; 1.0586x over previous
#include <cuda_runtime.h>
#include <cuda_fp16.h>
#include <cstdint>
#include <cstddef>

// Problem constants
#define BB 8
#define NSEQ 4096
#define NN 32768            // BB*NSEQ nodes
#define H 128
#define EDGES 524288
#define RREL 8
#define NLAYERS 2

#define PITCH_W 136         // fp16 elems per W smem row (272B)
#define PITCH_A 40          // fp16 elems per A-chunk smem row (80B; 32 data + 8 pad)

// ---- smem map for streaming GEMM kernels (fp16 element offsets) ----
#define SW_H   0
#define SA_OFF (128 * PITCH_W)                 // 17408
#define SA_SZ  (128 * PITCH_A)                 // 5120 per buffer
#define SM_ELEMS (SA_OFF + 2 * SA_SZ)          // 27648 fp16 = 55296 B

#define NMAT (1 + NLAYERS * (RREL + 1))        // 19 weight matrices
#define SCALE 64.0f
#define INV_SCALE2 (1.0f / 4096.0f)

// ---------------- scratch (static device globals; no allocation) ----------------
__device__ float g_Z[(size_t)NN * H];            // self-GEMM out / agg base (16 MB)
__device__ __half g_Y[(size_t)RREL * NN * H];    // per-relation messages, fp16 (64 MB)
__device__ __half g_Xf[(size_t)NN * H];          // node states, fp16 scaled x64 (8 MB)
__device__ __half g_Wh[(size_t)NMAT * H * H];    // weights fp16 (x64)
__device__ int g_degi[NN];                       // in-degree (int)
__device__ int g_off[NN];                        // CSR offsets (exclusive prefix of degi)
__device__ int g_cursor[NN];                     // scatter cursors
__device__ int g_epack[EDGES];                   // dst-bucketed packed edges: src | (r<<15)

// ---------------- helpers ----------------
__device__ __forceinline__ uint32_t smem_u32(const void* p) {
    uint32_t a;
    asm("{ .reg .u64 t; cvta.to.shared.u64 t, %1; cvt.u32.u64 %0, t; }" : "=r"(a) : "l"(p));
    return a;
}
__device__ __forceinline__ void cp_async16(uint32_t dst, const void* src) {
    asm volatile("cp.async.cg.shared.global [%0], [%1], 16;" :: "r"(dst), "l"(src));
}
__device__ __forceinline__ void cp_commit() {
    asm volatile("cp.async.commit_group;");
}
__device__ __forceinline__ void cp_wait0() {
    asm volatile("cp.async.wait_group 0;");
}
__device__ __forceinline__ void ldm_x4(uint32_t& r0, uint32_t& r1, uint32_t& r2, uint32_t& r3,
                                       uint32_t addr) {
    asm volatile("ldmatrix.sync.aligned.m8n8.x4.shared.b16 {%0,%1,%2,%3}, [%4];"
                 : "=r"(r0), "=r"(r1), "=r"(r2), "=r"(r3) : "r"(addr));
}
__device__ __forceinline__ void mma16816(float* d, const uint32_t* a, uint32_t b0, uint32_t b1) {
    asm volatile(
        "mma.sync.aligned.m16n8k16.row.col.f32.f16.f16.f32 "
        "{%0,%1,%2,%3}, {%4,%5,%6,%7}, {%8,%9}, {%0,%1,%2,%3};"
        : "+f"(d[0]), "+f"(d[1]), "+f"(d[2]), "+f"(d[3])
        : "r"(a[0]), "r"(a[1]), "r"(a[2]), "r"(a[3]), "r"(b0), "r"(b1));
}

// ---------------- embed: Xf = fp16(64*(concept_emb[cid]+kind_emb[kid])); zero degi -----
__global__ __launch_bounds__(256) void embed_kernel(const int* __restrict__ cid,
                                                    const int* __restrict__ kid,
                                                    const float* __restrict__ cemb,
                                                    const float* __restrict__ kemb) {
    int t = blockIdx.x * 256 + threadIdx.x;        // one float4 per thread
    if (t < NN) g_degi[t] = 0;
    int node = t >> 5;
    int q = t & 31;
    int c = __ldg(cid + node);
    int k = __ldg(kid + node);
    float4 a = __ldg(((const float4*)(cemb + (size_t)c * H)) + q);
    float4 b = __ldg(((const float4*)(kemb + (size_t)k * H)) + q);
    __half h[4];
    h[0] = __float2half(SCALE * (a.x + b.x));
    h[1] = __float2half(SCALE * (a.y + b.y));
    h[2] = __float2half(SCALE * (a.z + b.z));
    h[3] = __float2half(SCALE * (a.w + b.w));
    ((uint2*)g_Xf)[t] = *(const uint2*)h;
}

// ---------------- degree (int) ----------------
__global__ __launch_bounds__(256) void deg_kernel(const int* __restrict__ eidx) {
    int e = blockIdx.x * 256 + threadIdx.x;
    if (e < EDGES) atomicAdd(&g_degi[__ldg(eidx + EDGES + e)], 1);
}

// ---------------- single-CTA scan: off/cursor = exclusive prefix of degi ----------------
__global__ __launch_bounds__(1024) void scan_kernel() {
    __shared__ int s[1024];
    int tid = threadIdx.x;
    int base = tid * 32;
    int v[32];
    int sum = 0;
#pragma unroll
    for (int i = 0; i < 32; i++) { v[i] = g_degi[base + i]; sum += v[i]; }
    s[tid] = sum;
    __syncthreads();
    for (int off = 1; off < 1024; off <<= 1) {
        int t = (tid >= off) ? s[tid - off] : 0;
        __syncthreads();
        s[tid] += t;
        __syncthreads();
    }
    int run = s[tid] - sum;   // exclusive prefix of this thread's chunk
#pragma unroll
    for (int i = 0; i < 32; i++) {
        g_off[base + i] = run;
        g_cursor[base + i] = run;
        run += v[i];
    }
}

// ---------------- scatter: bucket edges by dst, packed src | (r<<15) ----------------
__global__ __launch_bounds__(256) void scatter_kernel(const int* __restrict__ eidx,
                                                      const int* __restrict__ etype) {
    int e = blockIdx.x * 256 + threadIdx.x;
    if (e >= EDGES) return;
    int src = __ldg(eidx + e);
    int dst = __ldg(eidx + EDGES + e);
    int r = __ldg(etype + e);
    int pos = atomicAdd(&g_cursor[dst], 1);
    g_epack[pos] = src | (r << 15);
}

// ---------------- all-weight fp16 conversion (proj + both layers, one launch) --------
// layout: [proj][L0: rel0..7, self][L1: rel0..7, self], each 16384 elems
__global__ __launch_bounds__(256) void convert_w_all_kernel(const float* __restrict__ projW,
                                                            const float* __restrict__ selfW,
                                                            const float* __restrict__ relW) {
    int t = blockIdx.x * 256 + threadIdx.x;
    int f8 = t * 8;
    if (f8 >= NMAT * H * H) return;
    const float* src;
    if (f8 < H * H) {
        src = projW + f8;
    } else {
        int g = f8 - H * H;
        int l = g / ((RREL + 1) * H * H);
        int r = g % ((RREL + 1) * H * H);
        if (r < RREL * H * H) src = relW + (size_t)l * RREL * H * H + r;
        else src = selfW + (size_t)l * H * H + (r - RREL * H * H);
    }
    float4 a = *(const float4*)src;
    float4 b = *(const float4*)(src + 4);
    float v[8] = {a.x, a.y, a.z, a.w, b.x, b.y, b.z, b.w};
    __half hi[8];
#pragma unroll
    for (int i = 0; i < 8; i++) hi[i] = __float2half(SCALE * v[i]);
    ((uint4*)g_Wh)[t] = *(const uint4*)hi;
}

// ---------------- 128x128x128 fp16 HMMA tile GEMM (1-chain, streaming A) ----------------
// O[m][g] = sum_k A[m][k]*W[g][k] (scaled ops; /4096 + bias in epilogue).
// W (fp16) resident in smem; A streamed in 4 k-chunks of 32 with cp.async double buffer.
// OUT_MODE 0: fp32 -> O (+bias).  OUT_MODE 1: fp16 x64 -> Oh (+bias).  OUT_MODE 2: fp16 raw.
template <int OUT_MODE>
__device__ __forceinline__ void tile_gemm(const __half* __restrict__ A_g,
                                          const __half* __restrict__ Wh_g,
                                          const float* __restrict__ bias,
                                          float* __restrict__ O,
                                          __half* __restrict__ Oh, int m0) {
    extern __shared__ __half sm[];
    const uint32_t sbase = smem_u32(sm);
    const int tid = threadIdx.x;
    const __half* Ag = A_g + (size_t)m0 * H;

    {
#pragma unroll
        for (int it = 0; it < 8; it++) {
            int i = tid + it * 256;           // 0..2047 uint4 chunks (16 per row)
            int r = i >> 4;
            int c = i & 15;
            uint32_t dst = sbase + (SW_H + r * PITCH_W + c * 8) * 2;
            cp_async16(dst, Wh_g + r * H + c * 8);
        }
#pragma unroll
        for (int it = 0; it < 2; it++) {
            int i = tid + it * 256;           // 0..511
            int r = i >> 2;
            int c = i & 3;
            uint32_t dst = sbase + (SA_OFF + r * PITCH_A + c * 8) * 2;
            cp_async16(dst, Ag + r * H + c * 8);
        }
        cp_commit();
        cp_wait0();
    }
    __syncthreads();

    const int wid = tid >> 5;
    const int lane = tid & 31;
    const int wm = wid >> 2;
    const int wn = wid & 3;

    float acc[4][4][4];
#pragma unroll
    for (int i = 0; i < 4; i++)
#pragma unroll
        for (int j = 0; j < 4; j++)
#pragma unroll
            for (int k = 0; k < 4; k++) acc[i][j][k] = 0.0f;

    const uint32_t lrow = lane & 15;
    const uint32_t lhalf = lane >> 4;
    const uint32_t aWh = sbase + (SW_H + (wn * 32 + lrow) * PITCH_W + lhalf * 8) * 2;
    const uint32_t aA0 = sbase + (SA_OFF + (wm * 64 + lrow) * PITCH_A + lhalf * 8) * 2;

#pragma unroll
    for (int kc = 0; kc < 4; kc++) {
        if (kc < 3) {
            int b = (kc + 1) & 1;
#pragma unroll
            for (int it = 0; it < 2; it++) {
                int i = tid + it * 256;
                int r = i >> 2;
                int c = i & 3;
                uint32_t dst = sbase + (SA_OFF + b * SA_SZ + r * PITCH_A + c * 8) * 2;
                cp_async16(dst, Ag + r * H + (kc + 1) * 32 + c * 8);
            }
            cp_commit();
        }
        const uint32_t aA = aA0 + (kc & 1) * (SA_SZ * 2);
#pragma unroll
        for (int kstep = 0; kstep < 2; kstep++) {
            const int ks = kc * 2 + kstep;
            const uint32_t wkoff = ks * 32;
            const uint32_t akoff = kstep * 32;
            uint32_t bh[2][4];
#pragma unroll
            for (int bi = 0; bi < 2; bi++) {
                ldm_x4(bh[bi][0], bh[bi][1], bh[bi][2], bh[bi][3],
                       aWh + bi * (16 * PITCH_W * 2) + wkoff);
            }
#pragma unroll
            for (int mi = 0; mi < 4; mi++) {
                uint32_t a[4];
                ldm_x4(a[0], a[1], a[2], a[3], aA + mi * (16 * PITCH_A * 2) + akoff);
#pragma unroll
                for (int bi = 0; bi < 2; bi++) {
                    mma16816(acc[mi][2 * bi + 0], a, bh[bi][0], bh[bi][2]);
                    mma16816(acc[mi][2 * bi + 1], a, bh[bi][1], bh[bi][3]);
                }
            }
        }
        if (kc < 3) {
            cp_wait0();
            __syncthreads();
        }
    }

    const int gID = lane >> 2;
    const int tig = lane & 3;
#pragma unroll
    for (int mi = 0; mi < 4; mi++) {
#pragma unroll
        for (int nt = 0; nt < 4; nt++) {
            int col = wn * 32 + nt * 8 + tig * 2;
            float b0 = 0.0f, b1 = 0.0f;
            if (OUT_MODE != 2 && bias) { b0 = __ldg(bias + col); b1 = __ldg(bias + col + 1); }
#pragma unroll
            for (int half = 0; half < 2; half++) {
                int row = m0 + wm * 64 + mi * 16 + gID + half * 8;
                float v0 = acc[mi][nt][2 * half + 0] * INV_SCALE2 + b0;
                float v1 = acc[mi][nt][2 * half + 1] * INV_SCALE2 + b1;
                if (OUT_MODE == 0) {
                    float2 fv = make_float2(v0, v1);
                    *(float2*)(O + (size_t)row * H + col) = fv;
                } else if (OUT_MODE == 1) {
                    __half2 hv;
                    hv.x = __float2half(SCALE * v0);
                    hv.y = __float2half(SCALE * v1);
                    *(__half2*)(Oh + (size_t)row * H + col) = hv;
                } else {
                    __half2 hv;
                    hv.x = __float2half(v0);
                    hv.y = __float2half(v1);
                    *(__half2*)(Oh + (size_t)row * H + col) = hv;
                }
            }
        }
    }
}

// proj: Xf = fp16 x64 of (E0 @ projW^T + projb), in-place over Xf
__global__ __launch_bounds__(256, 2) void mma_proj_kernel(const float* __restrict__ projb) {
    tile_gemm<1>(g_Xf, g_Wh, projb, nullptr, g_Xf, blockIdx.x * 128);
}

// grid.y = 9: m<8 -> Y[m] = X @ rel_W[m]^T (fp16 out) ; m==8 -> Z = X @ self_W^T + b (fp32)
__global__ __launch_bounds__(256, 2) void mma_layer_kernel(const float* __restrict__ selfb,
                                                           int l) {
    int m = blockIdx.y;
    size_t woff = (size_t)(1 + l * (RREL + 1) + m) * H * H;
    const __half* wh = g_Wh + woff;
    if (m < RREL) {
        tile_gemm<2>(g_Xf, wh, nullptr, nullptr, g_Y + (size_t)m * NN * H, blockIdx.x * 128);
    } else {
        tile_gemm<0>(g_Xf, wh, selfb, g_Z, nullptr, blockIdx.x * 128);
    }
}

// ---------------- CSR aggregation + fused relu epilogue ----------------
// Warp per dst node: gather its bucketed edges' Y rows, accumulate fp32, add Z row,
// relu, write Xf (layer 0) or masked out (layer 1). No atomics.
__global__ __launch_bounds__(256) void agg_fused_kernel(int layer, float* __restrict__ out,
                                                        const int* __restrict__ mask) {
    int w = (blockIdx.x * 256 + threadIdx.x) >> 5;   // dst node, grid covers exactly NN
    int lane = threadIdx.x & 31;
    int off = __ldg(&g_off[w]);
    int n = __ldg(&g_degi[w]);
    float inv = 1.0f / fmaxf((float)n, 1.0f);
    float4 acc = make_float4(0.0f, 0.0f, 0.0f, 0.0f);

    for (int b = 0; b < n; b += 32) {
        int m = min(32, n - b);
        int pk = (b + lane < n) ? __ldg(g_epack + off + b + lane) : 0;
        int j = 0;
        for (; j + 4 <= m; j += 4) {
            uint2 u[4];
#pragma unroll
            for (int q = 0; q < 4; q++) {
                int p = __shfl_sync(0xffffffffu, pk, j + q);
                const uint2* yrow = (const uint2*)(g_Y +
                    ((size_t)((p >> 15) & 7) * NN + (p & 0x7FFF)) * H);
                u[q] = __ldg(yrow + lane);
            }
#pragma unroll
            for (int q = 0; q < 4; q++) {
                __half2 h0 = *(__half2*)&u[q].x;
                __half2 h1 = *(__half2*)&u[q].y;
                float2 f0 = __half22float2(h0);
                float2 f1 = __half22float2(h1);
                acc.x += f0.x; acc.y += f0.y; acc.z += f1.x; acc.w += f1.y;
            }
        }
        for (; j < m; j++) {
            int p = __shfl_sync(0xffffffffu, pk, j);
            const uint2* yrow = (const uint2*)(g_Y +
                ((size_t)((p >> 15) & 7) * NN + (p & 0x7FFF)) * H);
            uint2 u = __ldg(yrow + lane);
            __half2 h0 = *(__half2*)&u.x;
            __half2 h1 = *(__half2*)&u.y;
            float2 f0 = __half22float2(h0);
            float2 f1 = __half22float2(h1);
            acc.x += f0.x; acc.y += f0.y; acc.z += f1.x; acc.w += f1.y;
        }
    }

    float4 z = *(((const float4*)(g_Z + (size_t)w * H)) + lane);
    float4 v;
    v.x = fmaxf(z.x + acc.x * inv, 0.0f);
    v.y = fmaxf(z.y + acc.y * inv, 0.0f);
    v.z = fmaxf(z.z + acc.z * inv, 0.0f);
    v.w = fmaxf(z.w + acc.w * inv, 0.0f);

    if (layer == 0) {
        __half h[4];
        h[0] = __float2half(SCALE * v.x);
        h[1] = __float2half(SCALE * v.y);
        h[2] = __float2half(SCALE * v.z);
        h[3] = __float2half(SCALE * v.w);
        ((uint2*)g_Xf)[w * 32 + lane] = *(const uint2*)h;
    } else {
        float mk = (float)__ldg(mask + w);
        v.x *= mk; v.y *= mk; v.z *= mk; v.w *= mk;
        ((float4*)out)[w * 32 + lane] = v;
    }
}

// ---------------- launch ----------------
extern "C" void kernel_launch(void* const* d_in, const int* in_sizes, int n_in,
                              void* d_out, int out_size) {
    const int* cid     = (const int*)d_in[0];
    const int* kid     = (const int*)d_in[1];
    const int* mask    = (const int*)d_in[2];
    const int* eidx    = (const int*)d_in[3];
    const int* etype   = (const int*)d_in[4];
    const float* cemb  = (const float*)d_in[5];
    const float* kemb  = (const float*)d_in[6];
    const float* projW = (const float*)d_in[7];
    const float* projb = (const float*)d_in[8];
    const float* selfW = (const float*)d_in[9];
    const float* selfb = (const float*)d_in[10];
    const float* relW  = (const float*)d_in[11];
    float* out = (float*)d_out;

    const int smem_bytes = SM_ELEMS * 2;   // 55296
    cudaFuncSetAttribute(mma_proj_kernel, cudaFuncAttributeMaxDynamicSharedMemorySize, smem_bytes);
    cudaFuncSetAttribute(mma_layer_kernel, cudaFuncAttributeMaxDynamicSharedMemorySize, smem_bytes);

    embed_kernel<<<(NN * 32) / 256, 256>>>(cid, kid, cemb, kemb);   // also zeroes degi
    deg_kernel<<<EDGES / 256, 256>>>(eidx);
    scan_kernel<<<1, 1024>>>();
    scatter_kernel<<<EDGES / 256, 256>>>(eidx, etype);
    convert_w_all_kernel<<<(NMAT * H * H / 8 + 255) / 256, 256>>>(projW, selfW, relW);
    mma_proj_kernel<<<NN / 128, 256, smem_bytes>>>(projb);

    for (int l = 0; l < NLAYERS; l++) {
        mma_layer_kernel<<<dim3(NN / 128, RREL + 1), 256, smem_bytes>>>(selfb + l * H, l);
        agg_fused_kernel<<<(NN * 32) / 256, 256>>>(l, out, mask);
    }
}